// round 1
// baseline (speedup 1.0000x reference)
#include <cuda_runtime.h>
#include <cuda_fp16.h>
#include <mma.h>

using namespace nvcuda;

#define BB 4
#define LL 2048
#define KK 48
#define HH 128
#define FFD 512
#define NN (BB*LL)          /* 8192 nodes */
#define NPB 4               /* nodes per block in msg kernels */
#define ROWS (NPB*KK)       /* 192 rows */

/* smem layout for msg kernel:
   [0      , 98304 ) Asm   half[192][256]   (union: Csm float[192][128])
   [98304  , 147456) Tsm   half[192][128]
   [147456 , 180224) Wsm   half[128][128]
   [180224 , 182272) S1s   float[4][128]                                  */
#define SMEM_BYTES 182272

// ---------------- device scratch (no allocation allowed) ----------------
__device__ __half g_W1h[384*HH];
__device__ __half g_W2h[HH*HH];
__device__ __half g_W3h[HH*HH];
__device__ __half g_W11h[384*HH];
__device__ __half g_W12h[HH*HH];
__device__ __half g_W13h[HH*HH];
__device__ __half g_hVh[NN*HH];     // fp16 of input h_V
__device__ __half g_hV2h[NN*HH];    // fp16 of updated h_V
__device__ float  g_dh[NN*HH];      // node-message sums

__device__ __forceinline__ float gelu_f(float x) {
    return 0.5f * x * (1.0f + erff(x * 0.7071067811865475f));
}

__device__ __forceinline__ float warp_sum(float x) {
    #pragma unroll
    for (int off = 16; off; off >>= 1) x += __shfl_xor_sync(0xffffffffu, x, off);
    return x;
}

// ---------------- K0: fp32 -> fp16 conversions ----------------
__global__ void convert_kernel(const float* __restrict__ W1, const float* __restrict__ W2,
                               const float* __restrict__ W3, const float* __restrict__ W11,
                               const float* __restrict__ W12, const float* __restrict__ W13,
                               const float* __restrict__ hV) {
    int i = blockIdx.x * blockDim.x + threadIdx.x;
    if (i < 49152) { g_W1h[i]  = __float2half(W1[i]);  return; } i -= 49152;
    if (i < 16384) { g_W2h[i]  = __float2half(W2[i]);  return; } i -= 16384;
    if (i < 16384) { g_W3h[i]  = __float2half(W3[i]);  return; } i -= 16384;
    if (i < 49152) { g_W11h[i] = __float2half(W11[i]); return; } i -= 49152;
    if (i < 16384) { g_W12h[i] = __float2half(W12[i]); return; } i -= 16384;
    if (i < 16384) { g_W13h[i] = __float2half(W13[i]); return; } i -= 16384;
    if (i < NN*HH) { g_hVh[i]  = __float2half(hV[i]); }
}

// ---------------- wmma helpers ----------------
using FragA = wmma::fragment<wmma::matrix_a, 16,16,16, __half, wmma::row_major>;
using FragB = wmma::fragment<wmma::matrix_b, 16,16,16, __half, wmma::row_major>;
using FragC = wmma::fragment<wmma::accumulator, 16,16,16, float>;

// Warp tile: rows [wm*48, wm*48+48), cols [wn*32, wn*32+32). acc[3][2].
__device__ __forceinline__ void gemm_accum(FragC acc[3][2], const __half* A, int lda,
                                           int acol0, const __half* Bsm, int ksteps,
                                           int wm, int wn) {
    for (int ks = 0; ks < ksteps; ks++) {
        FragB fb[2];
        #pragma unroll
        for (int j = 0; j < 2; j++)
            wmma::load_matrix_sync(fb[j], Bsm + (ks*16)*HH + wn*32 + j*16, HH);
        #pragma unroll
        for (int i = 0; i < 3; i++) {
            FragA fa;
            wmma::load_matrix_sync(fa, A + (wm*48 + i*16)*lda + acol0 + ks*16, lda);
            #pragma unroll
            for (int j = 0; j < 2; j++)
                wmma::mma_sync(acc[i][j], fa, fb[j], acc[i][j]);
        }
    }
}

// ---------------- K1 / K3: fused 3-layer message MLP ----------------
// NODE=true : out = g_dh  (masked sum over k, /30)
// NODE=false: out = h_E result (residual + LN with g3/be3)
template<bool NODE>
__global__ __launch_bounds__(512, 1)
void msg_kernel(const float* __restrict__ hE,
                const float* __restrict__ hv_f32,     // fp32 h_V (orig or updated)
                const __half* __restrict__ hvh,       // fp16 gather source
                const float* __restrict__ Wfull,      // fp32 [384,128]; rows 0..127 used
                const __half* __restrict__ Wbch,      // fp16 [384,128]; rows 128..383 used
                const __half* __restrict__ W2h,
                const __half* __restrict__ W3h,
                const float* __restrict__ b1,
                const float* __restrict__ b2,
                const float* __restrict__ b3,
                const int*   __restrict__ E_idx,
                const float* __restrict__ mask_attend,
                const float* __restrict__ g3,
                const float* __restrict__ be3,
                float* __restrict__ out)
{
    extern __shared__ char smem[];
    __half* Asm = (__half*)smem;                // [192][256]
    float*  Csm = (float*)smem;                 // [192][128] (aliases Asm)
    __half* Tsm = (__half*)(smem + 98304);      // [192][128]
    __half* Wsm = (__half*)(smem + 147456);     // [128][128]
    float*  S1s = (float*)(smem + 180224);      // [4][128]

    const int tid = threadIdx.x;
    const int node0 = blockIdx.x * NPB;
    const int w  = tid >> 5;
    const int wm = w & 3, wn = w >> 2;

    // ---- stage A: load [h_E | gathered h_V] into Asm (fp16) ----
    for (int idx = tid; idx < ROWS*32; idx += 512) {
        int r = idx >> 5, c4 = idx & 31;
        int nl = r / 48, k = r - nl*48;
        int e = (node0 + nl)*KK + k;
        float4 v = *(const float4*)(hE + (size_t)e*HH + c4*4);
        __half2* dst = (__half2*)(Asm + r*256 + c4*4);
        dst[0] = __floats2half2_rn(v.x, v.y);
        dst[1] = __floats2half2_rn(v.z, v.w);
    }
    for (int idx = tid; idx < ROWS*16; idx += 512) {
        int r = idx >> 4, s = idx & 15;
        int nl = r / 48, k = r - nl*48;
        int n  = node0 + nl;
        int nbr = (n & ~(LL-1)) + E_idx[n*KK + k];   // b*L + idx
        *(uint4*)(Asm + r*256 + 128 + s*8) = *(const uint4*)(hvh + (size_t)nbr*HH + s*8);
    }

    // ---- S1 = hv @ W1a + b1 (fp32 for accuracy; repeated across 48 edges) ----
    {
        int nl = tid >> 7, h = tid & 127;
        const float* hv = hv_f32 + (size_t)(node0 + nl)*HH;
        float s = b1[h];
        #pragma unroll 4
        for (int i = 0; i < HH; i++) s += hv[i] * Wfull[i*HH + h];
        S1s[nl*HH + h] = s;
    }
    __syncthreads();

    FragC acc[3][2];

    // ---- GEMM1: [192,256] @ Wbc[256,128] ----
    #pragma unroll
    for (int i = 0; i < 3; i++)
        #pragma unroll
        for (int j = 0; j < 2; j++) wmma::fill_fragment(acc[i][j], 0.0f);
    for (int chunk = 0; chunk < 2; chunk++) {
        for (int idx = tid; idx < 2048; idx += 512)
            ((uint4*)Wsm)[idx] = ((const uint4*)(Wbch + (128 + chunk*128)*HH))[idx];
        __syncthreads();
        gemm_accum(acc, Asm, 256, chunk*128, Wsm, 8, wm, wn);
        __syncthreads();
    }
    #pragma unroll
    for (int i = 0; i < 3; i++)
        #pragma unroll
        for (int j = 0; j < 2; j++)
            wmma::store_matrix_sync(Csm + (wm*48 + i*16)*HH + wn*32 + j*16,
                                    acc[i][j], HH, wmma::mem_row_major);
    __syncthreads();
    for (int idx = tid; idx < ROWS*HH; idx += 512) {
        int r = idx >> 7, h = idx & 127;
        float x = Csm[idx] + S1s[(r/48)*HH + h];
        Tsm[idx] = __float2half(gelu_f(x));
    }
    __syncthreads();

    // ---- GEMM2: T @ W2 ----
    for (int idx = tid; idx < 2048; idx += 512)
        ((uint4*)Wsm)[idx] = ((const uint4*)W2h)[idx];
    __syncthreads();
    #pragma unroll
    for (int i = 0; i < 3; i++)
        #pragma unroll
        for (int j = 0; j < 2; j++) wmma::fill_fragment(acc[i][j], 0.0f);
    gemm_accum(acc, Tsm, 128, 0, Wsm, 8, wm, wn);
    __syncthreads();
    #pragma unroll
    for (int i = 0; i < 3; i++)
        #pragma unroll
        for (int j = 0; j < 2; j++)
            wmma::store_matrix_sync(Csm + (wm*48 + i*16)*HH + wn*32 + j*16,
                                    acc[i][j], HH, wmma::mem_row_major);
    __syncthreads();
    for (int idx = tid; idx < ROWS*HH; idx += 512) {
        int h = idx & 127;
        Tsm[idx] = __float2half(gelu_f(Csm[idx] + b2[h]));
    }
    __syncthreads();

    // ---- GEMM3: T @ W3 ----
    for (int idx = tid; idx < 2048; idx += 512)
        ((uint4*)Wsm)[idx] = ((const uint4*)W3h)[idx];
    __syncthreads();
    #pragma unroll
    for (int i = 0; i < 3; i++)
        #pragma unroll
        for (int j = 0; j < 2; j++) wmma::fill_fragment(acc[i][j], 0.0f);
    gemm_accum(acc, Tsm, 128, 0, Wsm, 8, wm, wn);
    __syncthreads();
    #pragma unroll
    for (int i = 0; i < 3; i++)
        #pragma unroll
        for (int j = 0; j < 2; j++)
            wmma::store_matrix_sync(Csm + (wm*48 + i*16)*HH + wn*32 + j*16,
                                    acc[i][j], HH, wmma::mem_row_major);
    __syncthreads();

    if (NODE) {
        // masked sum over k, /SCALE
        int nl = tid >> 7, h = tid & 127;
        int n  = node0 + nl;
        float bb3 = b3[h];
        float s = 0.0f;
        #pragma unroll 4
        for (int k = 0; k < KK; k++) {
            float m = mask_attend[n*KK + k];
            s += m * (Csm[(nl*48 + k)*HH + h] + bb3);
        }
        out[(size_t)n*HH + h] = s * (1.0f/30.0f);
    } else {
        // per-edge residual + LayerNorm(g3, be3)
        int lane = tid & 31;
        for (int r = w; r < ROWS; r += 16) {
            int nl = r / 48, k = r - nl*48;
            size_t eoff = (size_t)((node0 + nl)*KK + k) * HH;
            float x[4]; float m = 0.0f;
            #pragma unroll
            for (int q = 0; q < 4; q++) {
                int h = lane + 32*q;
                x[q] = Csm[r*HH + h] + b3[h] + hE[eoff + h];
                m += x[q];
            }
            m = warp_sum(m) * (1.0f/128.0f);
            float var = 0.0f;
            #pragma unroll
            for (int q = 0; q < 4; q++) { float d = x[q]-m; var += d*d; }
            var = warp_sum(var) * (1.0f/128.0f);
            float rs = rsqrtf(var + 1e-5f);
            #pragma unroll
            for (int q = 0; q < 4; q++) {
                int h = lane + 32*q;
                out[eoff + h] = (x[q]-m)*rs*g3[h] + be3[h];
            }
        }
    }
}

// ---------------- K2: LN1 + FFN + LN2 + mask ----------------
__global__ __launch_bounds__(512)
void ffn_kernel(const float* __restrict__ hV, const float* __restrict__ dh,
                const float* __restrict__ g1, const float* __restrict__ be1,
                const float* __restrict__ g2, const float* __restrict__ be2,
                const float* __restrict__ Win, const float* __restrict__ binf,
                const float* __restrict__ Wout, const float* __restrict__ bout,
                const float* __restrict__ mask_V,
                float* __restrict__ outV, __half* __restrict__ outVh)
{
    __shared__ float v[16*HH];    // 8 KB
    __shared__ float f[16*FFD];   // 32 KB
    const int tid = threadIdx.x;
    const int node0 = blockIdx.x * 16;
    const int wp = tid >> 5, lane = tid & 31;

    // LN1 over (hV + dh): one warp per node
    {
        int n = node0 + wp;
        float u[4]; float m = 0.0f;
        #pragma unroll
        for (int q = 0; q < 4; q++) {
            int h = lane + 32*q;
            u[q] = hV[(size_t)n*HH + h] + dh[(size_t)n*HH + h];
            m += u[q];
        }
        m = warp_sum(m) * (1.0f/128.0f);
        float var = 0.0f;
        #pragma unroll
        for (int q = 0; q < 4; q++) { float d = u[q]-m; var += d*d; }
        var = warp_sum(var) * (1.0f/128.0f);
        float rs = rsqrtf(var + 1e-5f);
        #pragma unroll
        for (int q = 0; q < 4; q++) {
            int h = lane + 32*q;
            v[wp*HH + h] = (u[q]-m)*rs*g1[h] + be1[h];
        }
    }
    __syncthreads();

    // layer A: f = gelu(v @ Win + bin). thread owns 4 j x 4 nodes.
    {
        int jb = (tid & 127) * 4;
        int qn = tid >> 7;                    // nodes qn, qn+4, qn+8, qn+12
        float fr[4][4];
        #pragma unroll
        for (int a = 0; a < 4; a++)
            #pragma unroll
            for (int t = 0; t < 4; t++) fr[a][t] = binf[jb+t];
        for (int i = 0; i < HH; i++) {
            float4 wv = *(const float4*)(Win + i*FFD + jb);
            #pragma unroll
            for (int a = 0; a < 4; a++) {
                float vv = v[(qn + 4*a)*HH + i];
                fr[a][0] += vv*wv.x; fr[a][1] += vv*wv.y;
                fr[a][2] += vv*wv.z; fr[a][3] += vv*wv.w;
            }
        }
        #pragma unroll
        for (int a = 0; a < 4; a++)
            #pragma unroll
            for (int t = 0; t < 4; t++)
                f[(qn + 4*a)*FFD + jb + t] = gelu_f(fr[a][t]);
    }
    __syncthreads();

    // layer B: u2 = v + f @ Wout + bout. one warp per node, 4 h per thread.
    {
        int hb = (tid & 31) * 4;
        int ng = tid >> 5;                    // node index in block
        float acc4[4];
        #pragma unroll
        for (int t = 0; t < 4; t++) acc4[t] = bout[hb+t];
        for (int j = 0; j < FFD; j++) {
            float fv = f[ng*FFD + j];
            float4 wv = *(const float4*)(Wout + j*HH + hb);
            acc4[0] += fv*wv.x; acc4[1] += fv*wv.y;
            acc4[2] += fv*wv.z; acc4[3] += fv*wv.w;
        }
        #pragma unroll
        for (int t = 0; t < 4; t++) v[ng*HH + hb + t] += acc4[t];
    }
    __syncthreads();

    // LN2 + mask_V
    {
        int n = node0 + wp;
        float x[4]; float m = 0.0f;
        #pragma unroll
        for (int q = 0; q < 4; q++) { x[q] = v[wp*HH + lane + 32*q]; m += x[q]; }
        m = warp_sum(m) * (1.0f/128.0f);
        float var = 0.0f;
        #pragma unroll
        for (int q = 0; q < 4; q++) { float d = x[q]-m; var += d*d; }
        var = warp_sum(var) * (1.0f/128.0f);
        float rs = rsqrtf(var + 1e-5f);
        float mv = mask_V[n];
        #pragma unroll
        for (int q = 0; q < 4; q++) {
            int h = lane + 32*q;
            float o = ((x[q]-m)*rs*g2[h] + be2[h]) * mv;
            outV[(size_t)n*HH + h]  = o;
            outVh[(size_t)n*HH + h] = __float2half(o);
        }
    }
}

// ---------------- host ----------------
extern "C" void kernel_launch(void* const* d_in, const int* in_sizes, int n_in,
                              void* d_out, int out_size) {
    const float* h_V        = (const float*)d_in[0];
    const float* h_E        = (const float*)d_in[1];
    const float* mask_V     = (const float*)d_in[2];
    const float* mask_att   = (const float*)d_in[3];
    const float* W1   = (const float*)d_in[4];
    const float* b1   = (const float*)d_in[5];
    const float* W2   = (const float*)d_in[6];
    const float* b2   = (const float*)d_in[7];
    const float* W3   = (const float*)d_in[8];
    const float* b3   = (const float*)d_in[9];
    const float* W11  = (const float*)d_in[10];
    const float* b11  = (const float*)d_in[11];
    const float* W12  = (const float*)d_in[12];
    const float* b12  = (const float*)d_in[13];
    const float* W13  = (const float*)d_in[14];
    const float* b13  = (const float*)d_in[15];
    const float* Win  = (const float*)d_in[16];
    const float* binf = (const float*)d_in[17];
    const float* Wout = (const float*)d_in[18];
    const float* bout = (const float*)d_in[19];
    const float* g1   = (const float*)d_in[20];
    const float* be1  = (const float*)d_in[21];
    const float* g2   = (const float*)d_in[22];
    const float* be2  = (const float*)d_in[23];
    const float* g3   = (const float*)d_in[24];
    const float* be3  = (const float*)d_in[25];
    const int*   E_idx = (const int*)d_in[26];

    float* outV = (float*)d_out;
    float* outE = outV + (size_t)NN*HH;

    cudaFuncSetAttribute(msg_kernel<true>,  cudaFuncAttributeMaxDynamicSharedMemorySize, SMEM_BYTES);
    cudaFuncSetAttribute(msg_kernel<false>, cudaFuncAttributeMaxDynamicSharedMemorySize, SMEM_BYTES);

    __half *W1h, *W2h, *W3h, *W11h, *W12h, *W13h, *hVh, *hV2h;
    float* dhp;
    cudaGetSymbolAddress((void**)&W1h,  g_W1h);
    cudaGetSymbolAddress((void**)&W2h,  g_W2h);
    cudaGetSymbolAddress((void**)&W3h,  g_W3h);
    cudaGetSymbolAddress((void**)&W11h, g_W11h);
    cudaGetSymbolAddress((void**)&W12h, g_W12h);
    cudaGetSymbolAddress((void**)&W13h, g_W13h);
    cudaGetSymbolAddress((void**)&hVh,  g_hVh);
    cudaGetSymbolAddress((void**)&hV2h, g_hV2h);
    cudaGetSymbolAddress((void**)&dhp,  g_dh);

    convert_kernel<<<2368, 512>>>(W1, W2, W3, W11, W12, W13, h_V);

    msg_kernel<true><<<NN/NPB, 512, SMEM_BYTES>>>(
        h_E, h_V, hVh, W1, W1h, W2h, W3h, b1, b2, b3,
        E_idx, mask_att, g1, be1, dhp);

    ffn_kernel<<<NN/16, 512>>>(h_V, dhp, g1, be1, g2, be2,
                               Win, binf, Wout, bout, mask_V, outV, hV2h);

    msg_kernel<false><<<NN/NPB, 512, SMEM_BYTES>>>(
        h_E, outV, hV2h, W11, W11h, W12h, W13h, b11, b12, b13,
        E_idx, nullptr, g3, be3, outE);
}

// round 2
// speedup vs baseline: 2.1458x; 2.1458x over previous
#include <cuda_runtime.h>
#include <cuda_fp16.h>
#include <mma.h>

using namespace nvcuda;

#define BB 4
#define LL 2048
#define KK 48
#define HH 128
#define FFD 512
#define NN (BB*LL)          /* 8192 nodes */
#define NPB 2               /* nodes per block in msg kernels */
#define ROWS (NPB*KK)       /* 96 rows */
#define MSG_THREADS 256

/* padded smem layout (row strides chosen so stride%128B == 16B -> 4-bank
   rotation per row -> conflict-free ldmatrix):
   Asm  half[96][264]   (aliases Csm float[96][132])   50688 B
   Tsm  half[96][136]                                  26112 B
   Wsm  half[128][136]                                 34816 B
   S1s  float[2][128]                                   1024 B   */
#define ASM_LD 264
#define CSM_LD 132
#define TSM_LD 136
#define WSM_LD 136
#define OFF_TSM 50688
#define OFF_WSM 76800
#define OFF_S1S 111616
#define SMEM_BYTES 112640

// ---------------- device scratch (no allocation allowed) ----------------
__device__ __half g_W1h[384*HH];
__device__ __half g_W2h[HH*HH];
__device__ __half g_W3h[HH*HH];
__device__ __half g_W11h[384*HH];
__device__ __half g_W12h[HH*HH];
__device__ __half g_W13h[HH*HH];
__device__ __half g_hVh[NN*HH];     // fp16 of input h_V
__device__ __half g_hV2h[NN*HH];    // fp16 of updated h_V
__device__ float  g_dh[NN*HH];      // node-message sums
__device__ float  g_S1[NN*HH];      // precomputed hv @ W1a + b1

__device__ __forceinline__ float gelu_f(float x) {
    return 0.5f * x * (1.0f + erff(x * 0.7071067811865475f));
}

__device__ __forceinline__ float warp_sum(float x) {
    #pragma unroll
    for (int off = 16; off; off >>= 1) x += __shfl_xor_sync(0xffffffffu, x, off);
    return x;
}

// ---------------- K0: fp32 -> fp16 conversions ----------------
__global__ void convert_kernel(const float* __restrict__ W1, const float* __restrict__ W2,
                               const float* __restrict__ W3, const float* __restrict__ W11,
                               const float* __restrict__ W12, const float* __restrict__ W13,
                               const float* __restrict__ hV) {
    int i = blockIdx.x * blockDim.x + threadIdx.x;
    if (i < 49152) { g_W1h[i]  = __float2half(W1[i]);  return; } i -= 49152;
    if (i < 16384) { g_W2h[i]  = __float2half(W2[i]);  return; } i -= 16384;
    if (i < 16384) { g_W3h[i]  = __float2half(W3[i]);  return; } i -= 16384;
    if (i < 49152) { g_W11h[i] = __float2half(W11[i]); return; } i -= 49152;
    if (i < 16384) { g_W12h[i] = __float2half(W12[i]); return; } i -= 16384;
    if (i < 16384) { g_W13h[i] = __float2half(W13[i]); return; } i -= 16384;
    if (i < NN*HH) { g_hVh[i]  = __float2half(hV[i]); }
}

// ---------------- S1 precompute: S1 = hv @ W1a + b1 (fp32) ----------------
// block = 8 nodes x 128 h, 128 threads
__global__ __launch_bounds__(128)
void s1_kernel(const float* __restrict__ hv, const float* __restrict__ W,
               const float* __restrict__ b, float* __restrict__ out) {
    __shared__ float hvs[8][HH];
    const int n0 = blockIdx.x * 8;
    const int tid = threadIdx.x;
    for (int i = tid; i < 8*HH; i += 128) hvs[i >> 7][i & 127] = hv[(size_t)n0*HH + i];
    __syncthreads();
    float acc[8];
    float bb = b[tid];
    #pragma unroll
    for (int a = 0; a < 8; a++) acc[a] = bb;
    #pragma unroll 4
    for (int i = 0; i < HH; i++) {
        float w = W[i*HH + tid];
        #pragma unroll
        for (int a = 0; a < 8; a++) acc[a] += hvs[a][i] * w;
    }
    #pragma unroll
    for (int a = 0; a < 8; a++) out[(size_t)(n0 + a)*HH + tid] = acc[a];
}

// ---------------- wmma helpers ----------------
using FragA = wmma::fragment<wmma::matrix_a, 16,16,16, __half, wmma::row_major>;
using FragB = wmma::fragment<wmma::matrix_b, 16,16,16, __half, wmma::row_major>;
using FragC = wmma::fragment<wmma::accumulator, 16,16,16, float>;

// Warp tile: rows [wm*48, wm*48+48), cols [wn*32, wn*32+32). acc[3][2].
__device__ __forceinline__ void gemm_accum(FragC acc[3][2], const __half* A, int lda,
                                           int acol0, const __half* Bsm,
                                           int ksteps, int wm, int wn) {
    for (int ks = 0; ks < ksteps; ks++) {
        FragB fb[2];
        #pragma unroll
        for (int j = 0; j < 2; j++)
            wmma::load_matrix_sync(fb[j], Bsm + (ks*16)*WSM_LD + wn*32 + j*16, WSM_LD);
        #pragma unroll
        for (int i = 0; i < 3; i++) {
            FragA fa;
            wmma::load_matrix_sync(fa, A + (wm*48 + i*16)*lda + acol0 + ks*16, lda);
            #pragma unroll
            for (int j = 0; j < 2; j++)
                wmma::mma_sync(acc[i][j], fa, fb[j], acc[i][j]);
        }
    }
}

__device__ __forceinline__ void store_C(FragC acc[3][2], float* Csm, int wm, int wn) {
    #pragma unroll
    for (int i = 0; i < 3; i++)
        #pragma unroll
        for (int j = 0; j < 2; j++)
            wmma::store_matrix_sync(Csm + (wm*48 + i*16)*CSM_LD + wn*32 + j*16,
                                    acc[i][j], CSM_LD, wmma::mem_row_major);
}

__device__ __forceinline__ void zero_C(FragC acc[3][2]) {
    #pragma unroll
    for (int i = 0; i < 3; i++)
        #pragma unroll
        for (int j = 0; j < 2; j++) wmma::fill_fragment(acc[i][j], 0.0f);
}

// ---------------- K1 / K3: fused 3-layer message MLP ----------------
// NODE=true : out = g_dh  (masked sum over k, /30)
// NODE=false: out = h_E result (residual + LN with g3/be3)
template<bool NODE>
__global__ __launch_bounds__(MSG_THREADS, 2)
void msg_kernel(const float* __restrict__ hE,
                const float* __restrict__ S1g,        // precomputed hv@W1a+b1
                const __half* __restrict__ hvh,       // fp16 gather source
                const __half* __restrict__ Wbch,      // fp16 [384,128]; rows 128..383 used
                const __half* __restrict__ W2h,
                const __half* __restrict__ W3h,
                const float* __restrict__ b2,
                const float* __restrict__ b3,
                const int*   __restrict__ E_idx,
                const float* __restrict__ mask_attend,
                const float* __restrict__ g3,
                const float* __restrict__ be3,
                float* __restrict__ out)
{
    extern __shared__ char smem[];
    __half* Asm = (__half*)smem;                 // [96][264]
    float*  Csm = (float*)smem;                  // [96][132] (aliases Asm)
    __half* Tsm = (__half*)(smem + OFF_TSM);     // [96][136]
    __half* Wsm = (__half*)(smem + OFF_WSM);     // [128][136]
    float*  S1s = (float*)(smem + OFF_S1S);      // [2][128]

    const int tid = threadIdx.x;
    const int node0 = blockIdx.x * NPB;
    const int w  = tid >> 5;
    const int wm = w & 1, wn = w >> 1;

    // ---- stage A: load [h_E | gathered h_V] into Asm (fp16), S1 into smem ----
    for (int idx = tid; idx < ROWS*32; idx += MSG_THREADS) {
        int r = idx >> 5, c4 = idx & 31;
        int nl = r / 48, k = r - nl*48;
        int e = (node0 + nl)*KK + k;
        float4 v = *(const float4*)(hE + (size_t)e*HH + c4*4);
        __half2* dst = (__half2*)(Asm + r*ASM_LD + c4*4);
        dst[0] = __floats2half2_rn(v.x, v.y);
        dst[1] = __floats2half2_rn(v.z, v.w);
    }
    for (int idx = tid; idx < ROWS*16; idx += MSG_THREADS) {
        int r = idx >> 4, s = idx & 15;
        int nl = r / 48, k = r - nl*48;
        int n  = node0 + nl;
        int nbr = (n & ~(LL-1)) + E_idx[n*KK + k];   // b*L + idx
        *(uint4*)(Asm + r*ASM_LD + 128 + s*8) = *(const uint4*)(hvh + (size_t)nbr*HH + s*8);
    }
    S1s[tid] = S1g[(size_t)node0*HH + tid];          // 256 floats = 2 nodes

    FragC acc[3][2];

    // ---- GEMM1: [96,256] @ Wbc[256,128] (chunked weight staging) ----
    zero_C(acc);
    #pragma unroll
    for (int chunk = 0; chunk < 2; chunk++) {
        for (int idx = tid; idx < 2048; idx += MSG_THREADS) {
            int row = idx >> 4, c = idx & 15;
            *(uint4*)(Wsm + row*WSM_LD + c*8) =
                *(const uint4*)(Wbch + (128 + chunk*128)*HH + row*HH + c*8);
        }
        __syncthreads();
        gemm_accum(acc, Asm, ASM_LD, chunk*128, Wsm, 8, wm, wn);
        __syncthreads();
    }
    store_C(acc, Csm, wm, wn);
    __syncthreads();
    for (int idx = tid; idx < ROWS*HH; idx += MSG_THREADS) {
        int r = idx >> 7, h = idx & 127;
        float x = Csm[r*CSM_LD + h] + S1s[(r/48)*HH + h];
        Tsm[r*TSM_LD + h] = __float2half(gelu_f(x));
    }
    __syncthreads();

    // ---- GEMM2: T @ W2 ----
    for (int idx = tid; idx < 2048; idx += MSG_THREADS) {
        int row = idx >> 4, c = idx & 15;
        *(uint4*)(Wsm + row*WSM_LD + c*8) = *(const uint4*)(W2h + row*HH + c*8);
    }
    __syncthreads();
    zero_C(acc);
    gemm_accum(acc, Tsm, TSM_LD, 0, Wsm, 8, wm, wn);
    store_C(acc, Csm, wm, wn);
    __syncthreads();
    for (int idx = tid; idx < ROWS*HH; idx += MSG_THREADS) {
        int r = idx >> 7, h = idx & 127;
        Tsm[r*TSM_LD + h] = __float2half(gelu_f(Csm[r*CSM_LD + h] + b2[h]));
    }
    __syncthreads();

    // ---- GEMM3: T @ W3 ----
    for (int idx = tid; idx < 2048; idx += MSG_THREADS) {
        int row = idx >> 4, c = idx & 15;
        *(uint4*)(Wsm + row*WSM_LD + c*8) = *(const uint4*)(W3h + row*HH + c*8);
    }
    __syncthreads();
    zero_C(acc);
    gemm_accum(acc, Tsm, TSM_LD, 0, Wsm, 8, wm, wn);
    store_C(acc, Csm, wm, wn);
    __syncthreads();

    if (NODE) {
        // masked sum over k, /SCALE
        int nl = tid >> 7, h = tid & 127;
        int n  = node0 + nl;
        float bb3 = b3[h];
        float s = 0.0f;
        #pragma unroll 4
        for (int k = 0; k < KK; k++) {
            float m = mask_attend[n*KK + k];
            s += m * (Csm[(nl*48 + k)*CSM_LD + h] + bb3);
        }
        out[(size_t)n*HH + h] = s * (1.0f/30.0f);
    } else {
        // per-edge residual + LayerNorm(g3, be3)
        int lane = tid & 31;
        for (int r = w; r < ROWS; r += 8) {
            int nl = r / 48, k = r - nl*48;
            size_t eoff = (size_t)((node0 + nl)*KK + k) * HH;
            float x[4]; float m = 0.0f;
            #pragma unroll
            for (int q = 0; q < 4; q++) {
                int h = lane + 32*q;
                x[q] = Csm[r*CSM_LD + h] + b3[h] + hE[eoff + h];
                m += x[q];
            }
            m = warp_sum(m) * (1.0f/128.0f);
            float var = 0.0f;
            #pragma unroll
            for (int q = 0; q < 4; q++) { float d = x[q]-m; var += d*d; }
            var = warp_sum(var) * (1.0f/128.0f);
            float rs = rsqrtf(var + 1e-5f);
            #pragma unroll
            for (int q = 0; q < 4; q++) {
                int h = lane + 32*q;
                out[eoff + h] = (x[q]-m)*rs*g3[h] + be3[h];
            }
        }
    }
}

// ---------------- K2: LN1 + FFN + LN2 + mask ----------------
__global__ __launch_bounds__(512)
void ffn_kernel(const float* __restrict__ hV, const float* __restrict__ dh,
                const float* __restrict__ g1, const float* __restrict__ be1,
                const float* __restrict__ g2, const float* __restrict__ be2,
                const float* __restrict__ Win, const float* __restrict__ binf,
                const float* __restrict__ Wout, const float* __restrict__ bout,
                const float* __restrict__ mask_V,
                float* __restrict__ outV, __half* __restrict__ outVh)
{
    __shared__ float v[16*HH];    // 8 KB
    __shared__ float f[16*FFD];   // 32 KB
    const int tid = threadIdx.x;
    const int node0 = blockIdx.x * 16;
    const int wp = tid >> 5, lane = tid & 31;

    // LN1 over (hV + dh): one warp per node
    {
        int n = node0 + wp;
        float u[4]; float m = 0.0f;
        #pragma unroll
        for (int q = 0; q < 4; q++) {
            int h = lane + 32*q;
            u[q] = hV[(size_t)n*HH + h] + dh[(size_t)n*HH + h];
            m += u[q];
        }
        m = warp_sum(m) * (1.0f/128.0f);
        float var = 0.0f;
        #pragma unroll
        for (int q = 0; q < 4; q++) { float d = u[q]-m; var += d*d; }
        var = warp_sum(var) * (1.0f/128.0f);
        float rs = rsqrtf(var + 1e-5f);
        #pragma unroll
        for (int q = 0; q < 4; q++) {
            int h = lane + 32*q;
            v[wp*HH + h] = (u[q]-m)*rs*g1[h] + be1[h];
        }
    }
    __syncthreads();

    // layer A: f = gelu(v @ Win + bin). thread owns 4 j x 4 nodes.
    {
        int jb = (tid & 127) * 4;
        int qn = tid >> 7;                    // nodes qn, qn+4, qn+8, qn+12
        float fr[4][4];
        #pragma unroll
        for (int a = 0; a < 4; a++)
            #pragma unroll
            for (int t = 0; t < 4; t++) fr[a][t] = binf[jb+t];
        for (int i = 0; i < HH; i++) {
            float4 wv = *(const float4*)(Win + i*FFD + jb);
            #pragma unroll
            for (int a = 0; a < 4; a++) {
                float vv = v[(qn + 4*a)*HH + i];
                fr[a][0] += vv*wv.x; fr[a][1] += vv*wv.y;
                fr[a][2] += vv*wv.z; fr[a][3] += vv*wv.w;
            }
        }
        #pragma unroll
        for (int a = 0; a < 4; a++)
            #pragma unroll
            for (int t = 0; t < 4; t++)
                f[(qn + 4*a)*FFD + jb + t] = gelu_f(fr[a][t]);
    }
    __syncthreads();

    // layer B: u2 = v + f @ Wout + bout. one warp per node, 4 h per thread.
    {
        int hb = (tid & 31) * 4;
        int ng = tid >> 5;                    // node index in block
        float acc4[4];
        #pragma unroll
        for (int t = 0; t < 4; t++) acc4[t] = bout[hb+t];
        for (int j = 0; j < FFD; j++) {
            float fv = f[ng*FFD + j];
            float4 wv = *(const float4*)(Wout + j*HH + hb);
            acc4[0] += fv*wv.x; acc4[1] += fv*wv.y;
            acc4[2] += fv*wv.z; acc4[3] += fv*wv.w;
        }
        #pragma unroll
        for (int t = 0; t < 4; t++) v[ng*HH + hb + t] += acc4[t];
    }
    __syncthreads();

    // LN2 + mask_V
    {
        int n = node0 + wp;
        float x[4]; float m = 0.0f;
        #pragma unroll
        for (int q = 0; q < 4; q++) { x[q] = v[wp*HH + lane + 32*q]; m += x[q]; }
        m = warp_sum(m) * (1.0f/128.0f);
        float var = 0.0f;
        #pragma unroll
        for (int q = 0; q < 4; q++) { float d = x[q]-m; var += d*d; }
        var = warp_sum(var) * (1.0f/128.0f);
        float rs = rsqrtf(var + 1e-5f);
        float mv = mask_V[n];
        #pragma unroll
        for (int q = 0; q < 4; q++) {
            int h = lane + 32*q;
            float o = ((x[q]-m)*rs*g2[h] + be2[h]) * mv;
            outV[(size_t)n*HH + h]  = o;
            outVh[(size_t)n*HH + h] = __float2half(o);
        }
    }
}

// ---------------- host ----------------
extern "C" void kernel_launch(void* const* d_in, const int* in_sizes, int n_in,
                              void* d_out, int out_size) {
    const float* h_V        = (const float*)d_in[0];
    const float* h_E        = (const float*)d_in[1];
    const float* mask_V     = (const float*)d_in[2];
    const float* mask_att   = (const float*)d_in[3];
    const float* W1   = (const float*)d_in[4];
    const float* b1   = (const float*)d_in[5];
    const float* W2   = (const float*)d_in[6];
    const float* b2   = (const float*)d_in[7];
    const float* W3   = (const float*)d_in[8];
    const float* b3   = (const float*)d_in[9];
    const float* W11  = (const float*)d_in[10];
    const float* b11  = (const float*)d_in[11];
    const float* W12  = (const float*)d_in[12];
    const float* b12  = (const float*)d_in[13];
    const float* W13  = (const float*)d_in[14];
    const float* b13  = (const float*)d_in[15];
    const float* Win  = (const float*)d_in[16];
    const float* binf = (const float*)d_in[17];
    const float* Wout = (const float*)d_in[18];
    const float* bout = (const float*)d_in[19];
    const float* g1   = (const float*)d_in[20];
    const float* be1  = (const float*)d_in[21];
    const float* g2   = (const float*)d_in[22];
    const float* be2  = (const float*)d_in[23];
    const float* g3   = (const float*)d_in[24];
    const float* be3  = (const float*)d_in[25];
    const int*   E_idx = (const int*)d_in[26];

    float* outV = (float*)d_out;
    float* outE = outV + (size_t)NN*HH;

    cudaFuncSetAttribute(msg_kernel<true>,  cudaFuncAttributeMaxDynamicSharedMemorySize, SMEM_BYTES);
    cudaFuncSetAttribute(msg_kernel<false>, cudaFuncAttributeMaxDynamicSharedMemorySize, SMEM_BYTES);

    __half *W1h, *W2h, *W3h, *W11h, *W12h, *W13h, *hVh, *hV2h;
    float *dhp, *S1p;
    cudaGetSymbolAddress((void**)&W1h,  g_W1h);
    cudaGetSymbolAddress((void**)&W2h,  g_W2h);
    cudaGetSymbolAddress((void**)&W3h,  g_W3h);
    cudaGetSymbolAddress((void**)&W11h, g_W11h);
    cudaGetSymbolAddress((void**)&W12h, g_W12h);
    cudaGetSymbolAddress((void**)&W13h, g_W13h);
    cudaGetSymbolAddress((void**)&hVh,  g_hVh);
    cudaGetSymbolAddress((void**)&hV2h, g_hV2h);
    cudaGetSymbolAddress((void**)&dhp,  g_dh);
    cudaGetSymbolAddress((void**)&S1p,  g_S1);

    convert_kernel<<<2368, 512>>>(W1, W2, W3, W11, W12, W13, h_V);

    s1_kernel<<<NN/8, 128>>>(h_V, W1, b1, S1p);

    msg_kernel<true><<<NN/NPB, MSG_THREADS, SMEM_BYTES>>>(
        h_E, S1p, hVh, W1h, W2h, W3h, b2, b3,
        E_idx, mask_att, g1, be1, dhp);

    ffn_kernel<<<NN/16, 512>>>(h_V, dhp, g1, be1, g2, be2,
                               Win, binf, Wout, bout, mask_V, outV, hV2h);

    s1_kernel<<<NN/8, 128>>>(outV, W11, b11, S1p);

    msg_kernel<false><<<NN/NPB, MSG_THREADS, SMEM_BYTES>>>(
        h_E, S1p, hV2h, W11h, W12h, W13h, b12, b13,
        E_idx, nullptr, g3, be3, outE);
}

// round 3
// speedup vs baseline: 2.2048x; 1.0275x over previous
#include <cuda_runtime.h>
#include <cuda_fp16.h>
#include <mma.h>

using namespace nvcuda;

#define BB 4
#define LL 2048
#define KK 48
#define HH 128
#define FFD 512
#define NN (BB*LL)          /* 8192 nodes */
#define NPB 2               /* nodes per block in msg kernels */
#define ROWS (NPB*KK)       /* 96 rows */
#define MSG_THREADS 256

/* padded smem (row stride % 128B == 16B -> conflict-free ldmatrix) */
#define ASM_LD 264
#define CSM_LD 132
#define TSM_LD 136
#define WSM_LD 136
#define OFF_TSM 50688
#define OFF_WSM 76800
#define OFF_S1S 111616
#define SMEM_BYTES 112640

/* ffn smem layout */
#define FFN_OFF_V 0            /* half [64][136]  17408 */
#define FFN_OFF_F 17408        /* half [64][136]  17408 */
#define FFN_OFF_W 34816        /* half [128][136] 34816 */
#define FFN_OFF_C 69632        /* float[64][132]  33792 */
#define FFN_SMEM 103424

// ---------------- device scratch (no allocation allowed) ----------------
__device__ __half g_W1h[384*HH];
__device__ __half g_W2h[HH*HH];
__device__ __half g_W3h[HH*HH];
__device__ __half g_W11h[384*HH];
__device__ __half g_W12h[HH*HH];
__device__ __half g_W13h[HH*HH];
__device__ __half g_Winh[HH*FFD];
__device__ __half g_Wouth[FFD*HH];
__device__ __half g_hVh[NN*HH];       // fp16 of input h_V
__device__ __half g_hV2h[NN*HH];      // fp16 of updated h_V
__device__ __half g_hEh[NN*KK*HH];    // fp16 of h_E
__device__ float  g_dh[NN*HH];        // node-message sums
__device__ float  g_S1[NN*HH];        // precomputed hv @ W1a + b1
__device__ float  g_vln[NN*HH];       // fp32 LN1 output (ffn residual)

__device__ __forceinline__ float gelu_f(float x) {
    return 0.5f * x * (1.0f + erff(x * 0.7071067811865475f));
}

__device__ __forceinline__ float warp_sum(float x) {
    #pragma unroll
    for (int off = 16; off; off >>= 1) x += __shfl_xor_sync(0xffffffffu, x, off);
    return x;
}

// ---------------- K0a: weights + hV fp32 -> fp16 ----------------
__global__ void convert_w_kernel(const float* __restrict__ W1, const float* __restrict__ W2,
                                 const float* __restrict__ W3, const float* __restrict__ W11,
                                 const float* __restrict__ W12, const float* __restrict__ W13,
                                 const float* __restrict__ Win, const float* __restrict__ Wout,
                                 const float* __restrict__ hV) {
    int i = blockIdx.x * blockDim.x + threadIdx.x;
    if (i < 49152) { g_W1h[i]  = __float2half(W1[i]);  return; } i -= 49152;
    if (i < 16384) { g_W2h[i]  = __float2half(W2[i]);  return; } i -= 16384;
    if (i < 16384) { g_W3h[i]  = __float2half(W3[i]);  return; } i -= 16384;
    if (i < 49152) { g_W11h[i] = __float2half(W11[i]); return; } i -= 49152;
    if (i < 16384) { g_W12h[i] = __float2half(W12[i]); return; } i -= 16384;
    if (i < 16384) { g_W13h[i] = __float2half(W13[i]); return; } i -= 16384;
    if (i < 65536) { g_Winh[i] = __float2half(Win[i]); return; } i -= 65536;
    if (i < 65536) { g_Wouth[i]= __float2half(Wout[i]);return; } i -= 65536;
    if (i < NN*HH) { g_hVh[i]  = __float2half(hV[i]); }
}

// ---------------- K0b: h_E fp32 -> fp16 (vectorized) ----------------
__global__ void convert_e_kernel(const float* __restrict__ hE) {
    int i = blockIdx.x * blockDim.x + threadIdx.x;   // one float4
    float4 v = *(const float4*)(hE + (size_t)i*4);
    __half2* dst = (__half2*)(g_hEh + (size_t)i*4);
    dst[0] = __floats2half2_rn(v.x, v.y);
    dst[1] = __floats2half2_rn(v.z, v.w);
}

// ---------------- S1 precompute: S1 = hv @ W1a + b1 (fp32) ----------------
__global__ __launch_bounds__(128)
void s1_kernel(const float* __restrict__ hv, const float* __restrict__ W,
               const float* __restrict__ b, float* __restrict__ out) {
    __shared__ float hvs[8][HH];
    const int n0 = blockIdx.x * 8;
    const int tid = threadIdx.x;
    for (int i = tid; i < 8*HH; i += 128) hvs[i >> 7][i & 127] = hv[(size_t)n0*HH + i];
    __syncthreads();
    float acc[8];
    float bb = b[tid];
    #pragma unroll
    for (int a = 0; a < 8; a++) acc[a] = bb;
    #pragma unroll 4
    for (int i = 0; i < HH; i++) {
        float w = W[i*HH + tid];
        #pragma unroll
        for (int a = 0; a < 8; a++) acc[a] += hvs[a][i] * w;
    }
    #pragma unroll
    for (int a = 0; a < 8; a++) out[(size_t)(n0 + a)*HH + tid] = acc[a];
}

// ---------------- wmma helpers ----------------
using FragA = wmma::fragment<wmma::matrix_a, 16,16,16, __half, wmma::row_major>;
using FragB = wmma::fragment<wmma::matrix_b, 16,16,16, __half, wmma::row_major>;
using FragC = wmma::fragment<wmma::accumulator, 16,16,16, float>;

// msg warp tile: rows [wm*48,+48), cols [wn*32,+32). acc[3][2].
__device__ __forceinline__ void gemm_accum(FragC acc[3][2], const __half* A, int lda,
                                           int acol0, const __half* Bsm,
                                           int ksteps, int wm, int wn) {
    for (int ks = 0; ks < ksteps; ks++) {
        FragB fb[2];
        #pragma unroll
        for (int j = 0; j < 2; j++)
            wmma::load_matrix_sync(fb[j], Bsm + (ks*16)*WSM_LD + wn*32 + j*16, WSM_LD);
        #pragma unroll
        for (int i = 0; i < 3; i++) {
            FragA fa;
            wmma::load_matrix_sync(fa, A + (wm*48 + i*16)*lda + acol0 + ks*16, lda);
            #pragma unroll
            for (int j = 0; j < 2; j++)
                wmma::mma_sync(acc[i][j], fa, fb[j], acc[i][j]);
        }
    }
}

__device__ __forceinline__ void store_C(FragC acc[3][2], float* Csm, int wm, int wn) {
    #pragma unroll
    for (int i = 0; i < 3; i++)
        #pragma unroll
        for (int j = 0; j < 2; j++)
            wmma::store_matrix_sync(Csm + (wm*48 + i*16)*CSM_LD + wn*32 + j*16,
                                    acc[i][j], CSM_LD, wmma::mem_row_major);
}

__device__ __forceinline__ void zero_C(FragC acc[3][2]) {
    #pragma unroll
    for (int i = 0; i < 3; i++)
        #pragma unroll
        for (int j = 0; j < 2; j++) wmma::fill_fragment(acc[i][j], 0.0f);
}

// ---------------- K1 / K3: fused 3-layer message MLP ----------------
template<bool NODE>
__global__ __launch_bounds__(MSG_THREADS, 2)
void msg_kernel(const float* __restrict__ hE,         // fp32 residual (NODE=false)
                const __half* __restrict__ hEh,       // fp16 h_E (A operand)
                const float* __restrict__ S1g,        // precomputed hv@W1a+b1
                const __half* __restrict__ hvh,       // fp16 gather source
                const __half* __restrict__ Wbch,      // fp16 [384,128]; rows 128..383 used
                const __half* __restrict__ W2h,
                const __half* __restrict__ W3h,
                const float* __restrict__ b2,
                const float* __restrict__ b3,
                const int*   __restrict__ E_idx,
                const float* __restrict__ mask_attend,
                const float* __restrict__ g3,
                const float* __restrict__ be3,
                float* __restrict__ out)
{
    extern __shared__ char smem[];
    __half* Asm = (__half*)smem;                 // [96][264]
    float*  Csm = (float*)smem;                  // [96][132] (aliases Asm)
    __half* Tsm = (__half*)(smem + OFF_TSM);     // [96][136]
    __half* Wsm = (__half*)(smem + OFF_WSM);     // [128][136]
    float*  S1s = (float*)(smem + OFF_S1S);      // [2][128]

    const int tid = threadIdx.x;
    const int node0 = blockIdx.x * NPB;
    const int w  = tid >> 5;
    const int wm = w & 1, wn = w >> 1;

    // ---- phase0: A load (fp16 copies) + S1 + stage W1 chunk0 ----
    for (int idx = tid; idx < ROWS*16; idx += MSG_THREADS) {
        int r = idx >> 4, s = idx & 15;
        int nl = r / 48, k = r - nl*48;
        size_t e = (size_t)((node0 + nl)*KK + k);
        *(uint4*)(Asm + r*ASM_LD + s*8) = *(const uint4*)(hEh + e*HH + s*8);
    }
    for (int idx = tid; idx < ROWS*16; idx += MSG_THREADS) {
        int r = idx >> 4, s = idx & 15;
        int nl = r / 48, k = r - nl*48;
        int n  = node0 + nl;
        int nbr = (n & ~(LL-1)) + E_idx[n*KK + k];   // b*L + idx
        *(uint4*)(Asm + r*ASM_LD + 128 + s*8) = *(const uint4*)(hvh + (size_t)nbr*HH + s*8);
    }
    S1s[tid] = S1g[(size_t)node0*HH + tid];
    for (int idx = tid; idx < 2048; idx += MSG_THREADS) {
        int row = idx >> 4, c = idx & 15;
        *(uint4*)(Wsm + row*WSM_LD + c*8) = *(const uint4*)(Wbch + (128 + row)*HH + c*8);
    }
    __syncthreads();

    FragC acc[3][2];

    // ---- GEMM1 chunk0: A[:,0:128] (hE) @ W1 rows 128..255 ----
    zero_C(acc);
    gemm_accum(acc, Asm, ASM_LD, 0, Wsm, 8, wm, wn);
    __syncthreads();
    // stage W1 chunk1 (rows 256..383)
    for (int idx = tid; idx < 2048; idx += MSG_THREADS) {
        int row = idx >> 4, c = idx & 15;
        *(uint4*)(Wsm + row*WSM_LD + c*8) = *(const uint4*)(Wbch + (256 + row)*HH + c*8);
    }
    __syncthreads();
    gemm_accum(acc, Asm, ASM_LD, 128, Wsm, 8, wm, wn);
    __syncthreads();                     // all A reads done (Csm aliases Asm)
    store_C(acc, Csm, wm, wn);
    __syncthreads();

    // ---- epilogue1 + stage W2 (same phase; disjoint smem) ----
    for (int idx = tid; idx < ROWS*HH; idx += MSG_THREADS) {
        int r = idx >> 7, h = idx & 127;
        float x = Csm[r*CSM_LD + h] + S1s[(r/48)*HH + h];
        Tsm[r*TSM_LD + h] = __float2half(gelu_f(x));
    }
    for (int idx = tid; idx < 2048; idx += MSG_THREADS) {
        int row = idx >> 4, c = idx & 15;
        *(uint4*)(Wsm + row*WSM_LD + c*8) = *(const uint4*)(W2h + row*HH + c*8);
    }
    __syncthreads();

    // ---- GEMM2 ----
    zero_C(acc);
    gemm_accum(acc, Tsm, TSM_LD, 0, Wsm, 8, wm, wn);
    store_C(acc, Csm, wm, wn);           // Csm dead since epi1; safe pre-sync
    __syncthreads();

    // ---- epilogue2 + stage W3 ----
    for (int idx = tid; idx < ROWS*HH; idx += MSG_THREADS) {
        int r = idx >> 7, h = idx & 127;
        Tsm[r*TSM_LD + h] = __float2half(gelu_f(Csm[r*CSM_LD + h] + b2[h]));
    }
    for (int idx = tid; idx < 2048; idx += MSG_THREADS) {
        int row = idx >> 4, c = idx & 15;
        *(uint4*)(Wsm + row*WSM_LD + c*8) = *(const uint4*)(W3h + row*HH + c*8);
    }
    __syncthreads();

    // ---- GEMM3 ----
    zero_C(acc);
    gemm_accum(acc, Tsm, TSM_LD, 0, Wsm, 8, wm, wn);
    store_C(acc, Csm, wm, wn);
    __syncthreads();

    if (NODE) {
        int nl = tid >> 7, h = tid & 127;
        int n  = node0 + nl;
        float bb3 = b3[h];
        float s = 0.0f;
        #pragma unroll 4
        for (int k = 0; k < KK; k++) {
            float m = mask_attend[n*KK + k];
            s += m * (Csm[(nl*48 + k)*CSM_LD + h] + bb3);
        }
        out[(size_t)n*HH + h] = s * (1.0f/30.0f);
    } else {
        int lane = tid & 31;
        for (int r = w; r < ROWS; r += 8) {
            int nl = r / 48, k = r - nl*48;
            size_t eoff = (size_t)((node0 + nl)*KK + k) * HH;
            float x[4]; float m = 0.0f;
            #pragma unroll
            for (int q = 0; q < 4; q++) {
                int h = lane + 32*q;
                x[q] = Csm[r*CSM_LD + h] + b3[h] + hE[eoff + h];
                m += x[q];
            }
            m = warp_sum(m) * (1.0f/128.0f);
            float var = 0.0f;
            #pragma unroll
            for (int q = 0; q < 4; q++) { float d = x[q]-m; var += d*d; }
            var = warp_sum(var) * (1.0f/128.0f);
            float rs = rsqrtf(var + 1e-5f);
            #pragma unroll
            for (int q = 0; q < 4; q++) {
                int h = lane + 32*q;
                out[eoff + h] = (x[q]-m)*rs*g3[h] + be3[h];
            }
        }
    }
}

// ---------------- K2: LN1 + FFN (wmma) + LN2 + mask ----------------
// block = 64 nodes, 256 threads = 8 warps (4 row-groups x 2 col-groups)
__global__ __launch_bounds__(256, 2)
void ffn_wmma_kernel(const float* __restrict__ hV, const float* __restrict__ dh,
                     const float* __restrict__ g1, const float* __restrict__ be1,
                     const float* __restrict__ g2, const float* __restrict__ be2,
                     const __half* __restrict__ Winh, const float* __restrict__ binf,
                     const __half* __restrict__ Wouth, const float* __restrict__ bout,
                     const float* __restrict__ mask_V, float* __restrict__ vln,
                     float* __restrict__ outV, __half* __restrict__ outVh)
{
    extern __shared__ char smem[];
    __half* Vh  = (__half*)(smem + FFN_OFF_V);   // [64][136]
    __half* Fsm = (__half*)(smem + FFN_OFF_F);   // [64][136]
    __half* Wsm = (__half*)(smem + FFN_OFF_W);   // [128][136]
    float*  Csm = (float*)(smem + FFN_OFF_C);    // [64][132]

    const int tid = threadIdx.x;
    const int node0 = blockIdx.x * 64;
    const int wp = tid >> 5, lane = tid & 31;
    const int wm = wp & 3, wn = wp >> 2;

    // ---- LN1: each warp handles 8 nodes ----
    for (int i = 0; i < 8; i++) {
        int nl = wp*8 + i, n = node0 + nl;
        float u[4]; float m = 0.0f;
        #pragma unroll
        for (int q = 0; q < 4; q++) {
            int h = lane + 32*q;
            u[q] = hV[(size_t)n*HH + h] + dh[(size_t)n*HH + h];
            m += u[q];
        }
        m = warp_sum(m) * (1.0f/128.0f);
        float var = 0.0f;
        #pragma unroll
        for (int q = 0; q < 4; q++) { float d = u[q]-m; var += d*d; }
        var = warp_sum(var) * (1.0f/128.0f);
        float rs = rsqrtf(var + 1e-5f);
        #pragma unroll
        for (int q = 0; q < 4; q++) {
            int h = lane + 32*q;
            float vl = (u[q]-m)*rs*g1[h] + be1[h];
            Vh[nl*136 + h] = __float2half(vl);
            vln[(size_t)n*HH + h] = vl;
        }
    }
    __syncthreads();

    FragC acc2[4];
    #pragma unroll
    for (int j = 0; j < 4; j++) wmma::fill_fragment(acc2[j], 0.0f);

    for (int jc = 0; jc < 4; jc++) {
        // stage Win[:, jc*128:+128]  (row stride FFD)
        for (int idx = tid; idx < 2048; idx += 256) {
            int row = idx >> 4, c = idx & 15;
            *(uint4*)(Wsm + row*136 + c*8) =
                *(const uint4*)(Winh + (size_t)row*FFD + jc*128 + c*8);
        }
        __syncthreads();
        // GEMM1 chunk: [64,128] = Vh[64,128] @ Win_chunk
        FragC acc1[4];
        #pragma unroll
        for (int j = 0; j < 4; j++) wmma::fill_fragment(acc1[j], 0.0f);
        for (int ks = 0; ks < 8; ks++) {
            FragA fa;
            wmma::load_matrix_sync(fa, Vh + (wm*16)*136 + ks*16, 136);
            #pragma unroll
            for (int j = 0; j < 4; j++) {
                FragB fb;
                wmma::load_matrix_sync(fb, Wsm + (ks*16)*136 + wn*64 + j*16, 136);
                wmma::mma_sync(acc1[j], fa, fb, acc1[j]);
            }
        }
        #pragma unroll
        for (int j = 0; j < 4; j++)
            wmma::store_matrix_sync(Csm + (wm*16)*CSM_LD + wn*64 + j*16,
                                    acc1[j], CSM_LD, wmma::mem_row_major);
        __syncthreads();
        // epilogue (gelu -> Fsm fp16) + stage Wout chunk (same phase)
        for (int idx = tid; idx < 64*128; idx += 256) {
            int r = idx >> 7, h = idx & 127;
            Fsm[r*136 + h] = __float2half(gelu_f(Csm[r*CSM_LD + h] + binf[jc*128 + h]));
        }
        for (int idx = tid; idx < 2048; idx += 256) {
            int row = idx >> 4, c = idx & 15;
            *(uint4*)(Wsm + row*136 + c*8) =
                *(const uint4*)(Wouth + (size_t)(jc*128 + row)*HH + c*8);
        }
        __syncthreads();
        // GEMM2 accumulate: acc2 += Fsm @ Wout_chunk
        for (int ks = 0; ks < 8; ks++) {
            FragA fa;
            wmma::load_matrix_sync(fa, Fsm + (wm*16)*136 + ks*16, 136);
            #pragma unroll
            for (int j = 0; j < 4; j++) {
                FragB fb;
                wmma::load_matrix_sync(fb, Wsm + (ks*16)*136 + wn*64 + j*16, 136);
                wmma::mma_sync(acc2[j], fa, fb, acc2[j]);
            }
        }
        __syncthreads();
    }
    #pragma unroll
    for (int j = 0; j < 4; j++)
        wmma::store_matrix_sync(Csm + (wm*16)*CSM_LD + wn*64 + j*16,
                                acc2[j], CSM_LD, wmma::mem_row_major);
    __syncthreads();

    // ---- LN2 + mask: residual from fp32 vln ----
    for (int i = 0; i < 8; i++) {
        int nl = wp*8 + i, n = node0 + nl;
        float x[4]; float m = 0.0f;
        #pragma unroll
        for (int q = 0; q < 4; q++) {
            int h = lane + 32*q;
            x[q] = vln[(size_t)n*HH + h] + Csm[nl*CSM_LD + h] + bout[h];
            m += x[q];
        }
        m = warp_sum(m) * (1.0f/128.0f);
        float var = 0.0f;
        #pragma unroll
        for (int q = 0; q < 4; q++) { float d = x[q]-m; var += d*d; }
        var = warp_sum(var) * (1.0f/128.0f);
        float rs = rsqrtf(var + 1e-5f);
        float mv = mask_V[n];
        #pragma unroll
        for (int q = 0; q < 4; q++) {
            int h = lane + 32*q;
            float o = ((x[q]-m)*rs*g2[h] + be2[h]) * mv;
            outV[(size_t)n*HH + h]  = o;
            outVh[(size_t)n*HH + h] = __float2half(o);
        }
    }
}

// ---------------- host ----------------
extern "C" void kernel_launch(void* const* d_in, const int* in_sizes, int n_in,
                              void* d_out, int out_size) {
    const float* h_V      = (const float*)d_in[0];
    const float* h_E      = (const float*)d_in[1];
    const float* mask_V   = (const float*)d_in[2];
    const float* mask_att = (const float*)d_in[3];
    const float* W1   = (const float*)d_in[4];
    const float* b1   = (const float*)d_in[5];
    const float* W2   = (const float*)d_in[6];
    const float* b2   = (const float*)d_in[7];
    const float* W3   = (const float*)d_in[8];
    const float* b3   = (const float*)d_in[9];
    const float* W11  = (const float*)d_in[10];
    const float* b11  = (const float*)d_in[11];
    const float* W12  = (const float*)d_in[12];
    const float* b12  = (const float*)d_in[13];
    const float* W13  = (const float*)d_in[14];
    const float* b13  = (const float*)d_in[15];
    const float* Win  = (const float*)d_in[16];
    const float* binf = (const float*)d_in[17];
    const float* Wout = (const float*)d_in[18];
    const float* bout = (const float*)d_in[19];
    const float* g1   = (const float*)d_in[20];
    const float* be1  = (const float*)d_in[21];
    const float* g2   = (const float*)d_in[22];
    const float* be2  = (const float*)d_in[23];
    const float* g3   = (const float*)d_in[24];
    const float* be3  = (const float*)d_in[25];
    const int*   E_idx = (const int*)d_in[26];

    float* outV = (float*)d_out;
    float* outE = outV + (size_t)NN*HH;

    cudaFuncSetAttribute(msg_kernel<true>,  cudaFuncAttributeMaxDynamicSharedMemorySize, SMEM_BYTES);
    cudaFuncSetAttribute(msg_kernel<false>, cudaFuncAttributeMaxDynamicSharedMemorySize, SMEM_BYTES);
    cudaFuncSetAttribute(ffn_wmma_kernel,   cudaFuncAttributeMaxDynamicSharedMemorySize, FFN_SMEM);

    __half *W1h, *W2h, *W3h, *W11h, *W12h, *W13h, *Winh, *Wouth, *hVh, *hV2h, *hEh;
    float *dhp, *S1p, *vlnp;
    cudaGetSymbolAddress((void**)&W1h,  g_W1h);
    cudaGetSymbolAddress((void**)&W2h,  g_W2h);
    cudaGetSymbolAddress((void**)&W3h,  g_W3h);
    cudaGetSymbolAddress((void**)&W11h, g_W11h);
    cudaGetSymbolAddress((void**)&W12h, g_W12h);
    cudaGetSymbolAddress((void**)&W13h, g_W13h);
    cudaGetSymbolAddress((void**)&Winh, g_Winh);
    cudaGetSymbolAddress((void**)&Wouth,g_Wouth);
    cudaGetSymbolAddress((void**)&hVh,  g_hVh);
    cudaGetSymbolAddress((void**)&hV2h, g_hV2h);
    cudaGetSymbolAddress((void**)&hEh,  g_hEh);
    cudaGetSymbolAddress((void**)&dhp,  g_dh);
    cudaGetSymbolAddress((void**)&S1p,  g_S1);
    cudaGetSymbolAddress((void**)&vlnp, g_vln);

    convert_w_kernel<<<2624, 512>>>(W1, W2, W3, W11, W12, W13, Win, Wout, h_V);
    convert_e_kernel<<<24576, 512>>>(h_E);

    s1_kernel<<<NN/8, 128>>>(h_V, W1, b1, S1p);

    msg_kernel<true><<<NN/NPB, MSG_THREADS, SMEM_BYTES>>>(
        h_E, hEh, S1p, hVh, W1h, W2h, W3h, b2, b3,
        E_idx, mask_att, g1, be1, dhp);

    ffn_wmma_kernel<<<NN/64, 256, FFN_SMEM>>>(h_V, dhp, g1, be1, g2, be2,
                                              Winh, binf, Wouth, bout, mask_V,
                                              vlnp, outV, hV2h);

    s1_kernel<<<NN/8, 128>>>(outV, W11, b11, S1p);

    msg_kernel<false><<<NN/NPB, MSG_THREADS, SMEM_BYTES>>>(
        h_E, hEh, S1p, hV2h, W11h, W12h, W13h, b12, b13,
        E_idx, nullptr, g3, be3, outE);
}

// round 5
// speedup vs baseline: 2.9708x; 1.3474x over previous
#include <cuda_runtime.h>
#include <cuda_fp16.h>
#include <mma.h>
#include <cstdint>

using namespace nvcuda;

#define BB 4
#define LL 2048
#define KK 48
#define HH 128
#define FFD 512
#define NN (BB*LL)          /* 8192 nodes */
#define NPB 2               /* nodes per block in msg kernels */
#define ROWS (NPB*KK)       /* 96 rows */
#define MSG_THREADS 384     /* 12 warps: 3 m-groups x 4 n-groups */

/* padded smem (row stride % 128B == 16B -> conflict-free ldmatrix) */
#define ASM_LD 264
#define CSM_LD 132
#define TSM_LD 136
#define WSM_LD 136
#define OFF_TSM 50688
#define OFF_WSM 76800
#define OFF_S1S 111616
#define SMEM_BYTES 112640

/* ffn smem layout */
#define FFN_OFF_V 0            /* half [64][136]  17408 */
#define FFN_OFF_F 17408        /* half [64][136]  17408 */
#define FFN_OFF_W 34816        /* half [128][136] 34816 */
#define FFN_OFF_C 69632        /* float[64][132]  33792 */
#define FFN_SMEM 103424

// ---------------- device scratch (no allocation allowed) ----------------
__device__ __half g_W1h[384*HH];
__device__ __half g_W2h[HH*HH];
__device__ __half g_W3h[HH*HH];
__device__ __half g_W11h[384*HH];
__device__ __half g_W12h[HH*HH];
__device__ __half g_W13h[HH*HH];
__device__ __half g_Winh[HH*FFD];
__device__ __half g_Wouth[FFD*HH];
__device__ __half g_hVh[NN*HH];       // fp16 of input h_V
__device__ __half g_hV2h[NN*HH];      // fp16 of updated h_V
__device__ __half g_hEh[NN*KK*HH];    // fp16 of h_E
__device__ float  g_dh[NN*HH];        // node-message sums
__device__ float  g_S1[NN*HH];        // precomputed hv @ W1a + b1
__device__ float  g_vln[NN*HH];       // fp32 LN1 output (ffn residual)

__device__ __forceinline__ float gelu_f(float x) {
    return 0.5f * x * (1.0f + erff(x * 0.7071067811865475f));
}

__device__ __forceinline__ float warp_sum(float x) {
    #pragma unroll
    for (int off = 16; off; off >>= 1) x += __shfl_xor_sync(0xffffffffu, x, off);
    return x;
}

// 16B async copy global -> shared
__device__ __forceinline__ void cp16(void* dst_smem, const void* src) {
    unsigned int d = (unsigned int)__cvta_generic_to_shared(dst_smem);
    asm volatile("cp.async.cg.shared.global [%0], [%1], 16;\n" :: "r"(d), "l"(src));
}
__device__ __forceinline__ void cp_commit_wait_all() {
    asm volatile("cp.async.commit_group;\n");
    asm volatile("cp.async.wait_group 0;\n");
}

// ---------------- K0a: weights + hV fp32 -> fp16 ----------------
__global__ void convert_w_kernel(const float* __restrict__ W1, const float* __restrict__ W2,
                                 const float* __restrict__ W3, const float* __restrict__ W11,
                                 const float* __restrict__ W12, const float* __restrict__ W13,
                                 const float* __restrict__ Win, const float* __restrict__ Wout,
                                 const float* __restrict__ hV) {
    int i = blockIdx.x * blockDim.x + threadIdx.x;
    if (i < 49152) { g_W1h[i]  = __float2half(W1[i]);  return; } i -= 49152;
    if (i < 16384) { g_W2h[i]  = __float2half(W2[i]);  return; } i -= 16384;
    if (i < 16384) { g_W3h[i]  = __float2half(W3[i]);  return; } i -= 16384;
    if (i < 49152) { g_W11h[i] = __float2half(W11[i]); return; } i -= 49152;
    if (i < 16384) { g_W12h[i] = __float2half(W12[i]); return; } i -= 16384;
    if (i < 16384) { g_W13h[i] = __float2half(W13[i]); return; } i -= 16384;
    if (i < 65536) { g_Winh[i] = __float2half(Win[i]); return; } i -= 65536;
    if (i < 65536) { g_Wouth[i]= __float2half(Wout[i]);return; } i -= 65536;
    if (i < NN*HH) { g_hVh[i]  = __float2half(hV[i]); }
}

// ---------------- K0b: h_E fp32 -> fp16 (vectorized) ----------------
__global__ void convert_e_kernel(const float* __restrict__ hE) {
    int i = blockIdx.x * blockDim.x + threadIdx.x;   // one float4
    float4 v = *(const float4*)(hE + (size_t)i*4);
    __half2* dst = (__half2*)(g_hEh + (size_t)i*4);
    dst[0] = __floats2half2_rn(v.x, v.y);
    dst[1] = __floats2half2_rn(v.z, v.w);
}

// ---------------- S1 precompute: S1 = hv @ W1a + b1 (fp32) ----------------
__global__ __launch_bounds__(128)
void s1_kernel(const float* __restrict__ hv, const float* __restrict__ W,
               const float* __restrict__ b, float* __restrict__ out) {
    __shared__ float hvs[8][HH];
    const int n0 = blockIdx.x * 8;
    const int tid = threadIdx.x;
    for (int i = tid; i < 8*HH; i += 128) hvs[i >> 7][i & 127] = hv[(size_t)n0*HH + i];
    __syncthreads();
    float acc[8];
    float bb = b[tid];
    #pragma unroll
    for (int a = 0; a < 8; a++) acc[a] = bb;
    #pragma unroll 4
    for (int i = 0; i < HH; i++) {
        float w = W[i*HH + tid];
        #pragma unroll
        for (int a = 0; a < 8; a++) acc[a] += hvs[a][i] * w;
    }
    #pragma unroll
    for (int a = 0; a < 8; a++) out[(size_t)(n0 + a)*HH + tid] = acc[a];
}

// ---------------- wmma helpers ----------------
using FragA = wmma::fragment<wmma::matrix_a, 16,16,16, __half, wmma::row_major>;
using FragB = wmma::fragment<wmma::matrix_b, 16,16,16, __half, wmma::row_major>;
using FragC = wmma::fragment<wmma::accumulator, 16,16,16, float>;

// msg warp tile: rows [wm*32,+32), cols [wn*32,+32). acc[2][2].
__device__ __forceinline__ void gemm_accum(FragC acc[2][2], const __half* A, int lda,
                                           int acol0, const __half* Bsm,
                                           int ksteps, int wm, int wn) {
    for (int ks = 0; ks < ksteps; ks++) {
        FragB fb[2];
        #pragma unroll
        for (int j = 0; j < 2; j++)
            wmma::load_matrix_sync(fb[j], Bsm + (ks*16)*WSM_LD + wn*32 + j*16, WSM_LD);
        #pragma unroll
        for (int i = 0; i < 2; i++) {
            FragA fa;
            wmma::load_matrix_sync(fa, A + (wm*32 + i*16)*lda + acol0 + ks*16, lda);
            #pragma unroll
            for (int j = 0; j < 2; j++)
                wmma::mma_sync(acc[i][j], fa, fb[j], acc[i][j]);
        }
    }
}

__device__ __forceinline__ void store_C(FragC acc[2][2], float* Csm, int wm, int wn) {
    #pragma unroll
    for (int i = 0; i < 2; i++)
        #pragma unroll
        for (int j = 0; j < 2; j++)
            wmma::store_matrix_sync(Csm + (wm*32 + i*16)*CSM_LD + wn*32 + j*16,
                                    acc[i][j], CSM_LD, wmma::mem_row_major);
}

__device__ __forceinline__ void zero_C(FragC acc[2][2]) {
    #pragma unroll
    for (int i = 0; i < 2; i++)
        #pragma unroll
        for (int j = 0; j < 2; j++) wmma::fill_fragment(acc[i][j], 0.0f);
}

// ---------------- K1 / K3: fused 3-layer message MLP ----------------
template<bool NODE>
__global__ __launch_bounds__(MSG_THREADS, 2)
void msg_kernel(const float* __restrict__ hE,         // fp32 residual (NODE=false)
                const __half* __restrict__ hEh,       // fp16 h_E (A operand)
                const float* __restrict__ S1g,        // precomputed hv@W1a+b1
                const __half* __restrict__ hvh,       // fp16 gather source
                const __half* __restrict__ Wbch,      // fp16 [384,128]; rows 128..383 used
                const __half* __restrict__ W2h,
                const __half* __restrict__ W3h,
                const float* __restrict__ b2,
                const float* __restrict__ b3,
                const int*   __restrict__ E_idx,
                const float* __restrict__ mask_attend,
                const float* __restrict__ g3,
                const float* __restrict__ be3,
                float* __restrict__ out)
{
    extern __shared__ char smem[];
    __half* Asm = (__half*)smem;                 // [96][264]
    float*  Csm = (float*)smem;                  // [96][132] (aliases Asm)
    __half* Tsm = (__half*)(smem + OFF_TSM);     // [96][136]
    __half* Wsm = (__half*)(smem + OFF_WSM);     // [128][136]
    float*  S1s = (float*)(smem + OFF_S1S);      // [2][128]

    const int tid = threadIdx.x;
    const int node0 = blockIdx.x * NPB;
    const int w  = tid >> 5;
    const int wm = w % 3, wn = w / 3;            // 3 m-groups x 4 n-groups

    // ---- phase0: async A load + S1 + stage W1 chunk0 ----
    for (int idx = tid; idx < ROWS*16; idx += MSG_THREADS) {
        int r = idx >> 4, s = idx & 15;
        int nl = r / 48, k = r - nl*48;
        size_t e = (size_t)((node0 + nl)*KK + k);
        cp16(Asm + r*ASM_LD + s*8, hEh + e*HH + s*8);
    }
    for (int idx = tid; idx < ROWS*16; idx += MSG_THREADS) {
        int r = idx >> 4, s = idx & 15;
        int nl = r / 48, k = r - nl*48;
        int n  = node0 + nl;
        int nbr = (n & ~(LL-1)) + E_idx[n*KK + k];   // b*L + idx
        cp16(Asm + r*ASM_LD + 128 + s*8, hvh + (size_t)nbr*HH + s*8);
    }
    for (int idx = tid; idx < 2048; idx += MSG_THREADS) {
        int row = idx >> 4, c = idx & 15;
        cp16(Wsm + row*WSM_LD + c*8, Wbch + (128 + row)*HH + c*8);
    }
    if (tid < 2*HH) S1s[tid] = S1g[(size_t)node0*HH + tid];
    cp_commit_wait_all();
    __syncthreads();

    FragC acc[2][2];

    // ---- GEMM1 chunk0: A[:,0:128] (hE) @ W1 rows 128..255 ----
    zero_C(acc);
    gemm_accum(acc, Asm, ASM_LD, 0, Wsm, 8, wm, wn);
    __syncthreads();
    // stage W1 chunk1 (rows 256..383)
    for (int idx = tid; idx < 2048; idx += MSG_THREADS) {
        int row = idx >> 4, c = idx & 15;
        cp16(Wsm + row*WSM_LD + c*8, Wbch + (256 + row)*HH + c*8);
    }
    cp_commit_wait_all();
    __syncthreads();
    gemm_accum(acc, Asm, ASM_LD, 128, Wsm, 8, wm, wn);
    __syncthreads();                     // all A reads done (Csm aliases Asm)
    store_C(acc, Csm, wm, wn);
    __syncthreads();

    // ---- epilogue1 + stage W2 (same phase; disjoint smem) ----
    for (int idx = tid; idx < 2048; idx += MSG_THREADS) {
        int row = idx >> 4, c = idx & 15;
        cp16(Wsm + row*WSM_LD + c*8, W2h + row*HH + c*8);
    }
    for (int idx = tid; idx < ROWS*HH; idx += MSG_THREADS) {
        int r = idx >> 7, h = idx & 127;
        float x = Csm[r*CSM_LD + h] + S1s[(r/48)*HH + h];
        Tsm[r*TSM_LD + h] = __float2half(gelu_f(x));
    }
    cp_commit_wait_all();
    __syncthreads();

    // ---- GEMM2 ----
    zero_C(acc);
    gemm_accum(acc, Tsm, TSM_LD, 0, Wsm, 8, wm, wn);
    store_C(acc, Csm, wm, wn);           // Csm dead since epi1; safe pre-sync
    __syncthreads();

    // ---- epilogue2 + stage W3 ----
    for (int idx = tid; idx < 2048; idx += MSG_THREADS) {
        int row = idx >> 4, c = idx & 15;
        cp16(Wsm + row*WSM_LD + c*8, W3h + row*HH + c*8);
    }
    for (int idx = tid; idx < ROWS*HH; idx += MSG_THREADS) {
        int r = idx >> 7, h = idx & 127;
        Tsm[r*TSM_LD + h] = __float2half(gelu_f(Csm[r*CSM_LD + h] + b2[h]));
    }
    cp_commit_wait_all();
    __syncthreads();

    // ---- GEMM3 ----
    zero_C(acc);
    gemm_accum(acc, Tsm, TSM_LD, 0, Wsm, 8, wm, wn);
    store_C(acc, Csm, wm, wn);
    __syncthreads();

    if (NODE) {
        if (tid < 2*HH) {
            int nl = tid >> 7, h = tid & 127;
            int n  = node0 + nl;
            float bb3 = b3[h];
            float s = 0.0f;
            #pragma unroll 4
            for (int k = 0; k < KK; k++) {
                float m = mask_attend[n*KK + k];
                s += m * (Csm[(nl*48 + k)*CSM_LD + h] + bb3);
            }
            out[(size_t)n*HH + h] = s * (1.0f/30.0f);
        }
    } else {
        int lane = tid & 31;
        for (int r = w; r < ROWS; r += 12) {
            int nl = r / 48, k = r - nl*48;
            size_t eoff = (size_t)((node0 + nl)*KK + k) * HH;
            float x[4]; float m = 0.0f;
            #pragma unroll
            for (int q = 0; q < 4; q++) {
                int h = lane + 32*q;
                x[q] = Csm[r*CSM_LD + h] + b3[h] + hE[eoff + h];
                m += x[q];
            }
            m = warp_sum(m) * (1.0f/128.0f);
            float var = 0.0f;
            #pragma unroll
            for (int q = 0; q < 4; q++) { float d = x[q]-m; var += d*d; }
            var = warp_sum(var) * (1.0f/128.0f);
            float rs = rsqrtf(var + 1e-5f);
            #pragma unroll
            for (int q = 0; q < 4; q++) {
                int h = lane + 32*q;
                out[eoff + h] = (x[q]-m)*rs*g3[h] + be3[h];
            }
        }
    }
}

// ---------------- K2: LN1 + FFN (wmma) + LN2 + mask ----------------
__global__ __launch_bounds__(256, 2)
void ffn_wmma_kernel(const float* __restrict__ hV, const float* __restrict__ dh,
                     const float* __restrict__ g1, const float* __restrict__ be1,
                     const float* __restrict__ g2, const float* __restrict__ be2,
                     const __half* __restrict__ Winh, const float* __restrict__ binf,
                     const __half* __restrict__ Wouth, const float* __restrict__ bout,
                     const float* __restrict__ mask_V, float* __restrict__ vln,
                     float* __restrict__ outV, __half* __restrict__ outVh)
{
    extern __shared__ char smem[];
    __half* Vh  = (__half*)(smem + FFN_OFF_V);   // [64][136]
    __half* Fsm = (__half*)(smem + FFN_OFF_F);   // [64][136]
    __half* Wsm = (__half*)(smem + FFN_OFF_W);   // [128][136]
    float*  Csm = (float*)(smem + FFN_OFF_C);    // [64][132]

    const int tid = threadIdx.x;
    const int node0 = blockIdx.x * 64;
    const int wp = tid >> 5, lane = tid & 31;
    const int wm = wp & 3, wn = wp >> 2;

    // ---- LN1: each warp handles 8 nodes ----
    for (int i = 0; i < 8; i++) {
        int nl = wp*8 + i, n = node0 + nl;
        float u[4]; float m = 0.0f;
        #pragma unroll
        for (int q = 0; q < 4; q++) {
            int h = lane + 32*q;
            u[q] = hV[(size_t)n*HH + h] + dh[(size_t)n*HH + h];
            m += u[q];
        }
        m = warp_sum(m) * (1.0f/128.0f);
        float var = 0.0f;
        #pragma unroll
        for (int q = 0; q < 4; q++) { float d = u[q]-m; var += d*d; }
        var = warp_sum(var) * (1.0f/128.0f);
        float rs = rsqrtf(var + 1e-5f);
        #pragma unroll
        for (int q = 0; q < 4; q++) {
            int h = lane + 32*q;
            float vl = (u[q]-m)*rs*g1[h] + be1[h];
            Vh[nl*136 + h] = __float2half(vl);
            vln[(size_t)n*HH + h] = vl;
        }
    }
    __syncthreads();

    FragC acc2[4];
    #pragma unroll
    for (int j = 0; j < 4; j++) wmma::fill_fragment(acc2[j], 0.0f);

    for (int jc = 0; jc < 4; jc++) {
        for (int idx = tid; idx < 2048; idx += 256) {
            int row = idx >> 4, c = idx & 15;
            cp16(Wsm + row*136 + c*8, Winh + (size_t)row*FFD + jc*128 + c*8);
        }
        cp_commit_wait_all();
        __syncthreads();
        FragC acc1[4];
        #pragma unroll
        for (int j = 0; j < 4; j++) wmma::fill_fragment(acc1[j], 0.0f);
        for (int ks = 0; ks < 8; ks++) {
            FragA fa;
            wmma::load_matrix_sync(fa, Vh + (wm*16)*136 + ks*16, 136);
            #pragma unroll
            for (int j = 0; j < 4; j++) {
                FragB fb;
                wmma::load_matrix_sync(fb, Wsm + (ks*16)*136 + wn*64 + j*16, 136);
                wmma::mma_sync(acc1[j], fa, fb, acc1[j]);
            }
        }
        #pragma unroll
        for (int j = 0; j < 4; j++)
            wmma::store_matrix_sync(Csm + (wm*16)*CSM_LD + wn*64 + j*16,
                                    acc1[j], CSM_LD, wmma::mem_row_major);
        __syncthreads();
        for (int idx = tid; idx < 2048; idx += 256) {
            int row = idx >> 4, c = idx & 15;
            cp16(Wsm + row*136 + c*8, Wouth + (size_t)(jc*128 + row)*HH + c*8);
        }
        for (int idx = tid; idx < 64*128; idx += 256) {
            int r = idx >> 7, h = idx & 127;
            Fsm[r*136 + h] = __float2half(gelu_f(Csm[r*CSM_LD + h] + binf[jc*128 + h]));
        }
        cp_commit_wait_all();
        __syncthreads();
        for (int ks = 0; ks < 8; ks++) {
            FragA fa;
            wmma::load_matrix_sync(fa, Fsm + (wm*16)*136 + ks*16, 136);
            #pragma unroll
            for (int j = 0; j < 4; j++) {
                FragB fb;
                wmma::load_matrix_sync(fb, Wsm + (ks*16)*136 + wn*64 + j*16, 136);
                wmma::mma_sync(acc2[j], fa, fb, acc2[j]);
            }
        }
        __syncthreads();
    }
    #pragma unroll
    for (int j = 0; j < 4; j++)
        wmma::store_matrix_sync(Csm + (wm*16)*CSM_LD + wn*64 + j*16,
                                acc2[j], CSM_LD, wmma::mem_row_major);
    __syncthreads();

    for (int i = 0; i < 8; i++) {
        int nl = wp*8 + i, n = node0 + nl;
        float x[4]; float m = 0.0f;
        #pragma unroll
        for (int q = 0; q < 4; q++) {
            int h = lane + 32*q;
            x[q] = vln[(size_t)n*HH + h] + Csm[nl*CSM_LD + h] + bout[h];
            m += x[q];
        }
        m = warp_sum(m) * (1.0f/128.0f);
        float var = 0.0f;
        #pragma unroll
        for (int q = 0; q < 4; q++) { float d = x[q]-m; var += d*d; }
        var = warp_sum(var) * (1.0f/128.0f);
        float rs = rsqrtf(var + 1e-5f);
        float mv = mask_V[n];
        #pragma unroll
        for (int q = 0; q < 4; q++) {
            int h = lane + 32*q;
            float o = ((x[q]-m)*rs*g2[h] + be2[h]) * mv;
            outV[(size_t)n*HH + h]  = o;
            outVh[(size_t)n*HH + h] = __float2half(o);
        }
    }
}

// ---------------- host ----------------
extern "C" void kernel_launch(void* const* d_in, const int* in_sizes, int n_in,
                              void* d_out, int out_size) {
    const float* h_V      = (const float*)d_in[0];
    const float* h_E      = (const float*)d_in[1];
    const float* mask_V   = (const float*)d_in[2];
    const float* mask_att = (const float*)d_in[3];
    const float* W1   = (const float*)d_in[4];
    const float* b1   = (const float*)d_in[5];
    const float* W2   = (const float*)d_in[6];
    const float* b2   = (const float*)d_in[7];
    const float* W3   = (const float*)d_in[8];
    const float* b3   = (const float*)d_in[9];
    const float* W11  = (const float*)d_in[10];
    const float* b11  = (const float*)d_in[11];
    const float* W12  = (const float*)d_in[12];
    const float* b12  = (const float*)d_in[13];
    const float* W13  = (const float*)d_in[14];
    const float* b13  = (const float*)d_in[15];
    const float* Win  = (const float*)d_in[16];
    const float* binf = (const float*)d_in[17];
    const float* Wout = (const float*)d_in[18];
    const float* bout = (const float*)d_in[19];
    const float* g1   = (const float*)d_in[20];
    const float* be1  = (const float*)d_in[21];
    const float* g2   = (const float*)d_in[22];
    const float* be2  = (const float*)d_in[23];
    const float* g3   = (const float*)d_in[24];
    const float* be3  = (const float*)d_in[25];
    const int*   E_idx = (const int*)d_in[26];

    float* outV = (float*)d_out;
    float* outE = outV + (size_t)NN*HH;

    cudaFuncSetAttribute(msg_kernel<true>,  cudaFuncAttributeMaxDynamicSharedMemorySize, SMEM_BYTES);
    cudaFuncSetAttribute(msg_kernel<false>, cudaFuncAttributeMaxDynamicSharedMemorySize, SMEM_BYTES);
    cudaFuncSetAttribute(ffn_wmma_kernel,   cudaFuncAttributeMaxDynamicSharedMemorySize, FFN_SMEM);

    __half *W1h, *W2h, *W3h, *W11h, *W12h, *W13h, *Winh, *Wouth, *hVh, *hV2h, *hEh;
    float *dhp, *S1p, *vlnp;
    cudaGetSymbolAddress((void**)&W1h,  g_W1h);
    cudaGetSymbolAddress((void**)&W2h,  g_W2h);
    cudaGetSymbolAddress((void**)&W3h,  g_W3h);
    cudaGetSymbolAddress((void**)&W11h, g_W11h);
    cudaGetSymbolAddress((void**)&W12h, g_W12h);
    cudaGetSymbolAddress((void**)&W13h, g_W13h);
    cudaGetSymbolAddress((void**)&Winh, g_Winh);
    cudaGetSymbolAddress((void**)&Wouth,g_Wouth);
    cudaGetSymbolAddress((void**)&hVh,  g_hVh);
    cudaGetSymbolAddress((void**)&hV2h, g_hV2h);
    cudaGetSymbolAddress((void**)&hEh,  g_hEh);
    cudaGetSymbolAddress((void**)&dhp,  g_dh);
    cudaGetSymbolAddress((void**)&S1p,  g_S1);
    cudaGetSymbolAddress((void**)&vlnp, g_vln);

    convert_w_kernel<<<2624, 512>>>(W1, W2, W3, W11, W12, W13, Win, Wout, h_V);
    convert_e_kernel<<<24576, 512>>>(h_E);

    s1_kernel<<<NN/8, 128>>>(h_V, W1, b1, S1p);

    msg_kernel<true><<<NN/NPB, MSG_THREADS, SMEM_BYTES>>>(
        h_E, hEh, S1p, hVh, W1h, W2h, W3h, b2, b3,
        E_idx, mask_att, g1, be1, dhp);

    ffn_wmma_kernel<<<NN/64, 256, FFN_SMEM>>>(h_V, dhp, g1, be1, g2, be2,
                                              Winh, binf, Wouth, bout, mask_V,
                                              vlnp, outV, hV2h);

    s1_kernel<<<NN/8, 128>>>(outV, W11, b11, S1p);

    msg_kernel<false><<<NN/NPB, MSG_THREADS, SMEM_BYTES>>>(
        h_E, hEh, S1p, hV2h, W11h, W12h, W13h, b12, b13,
        E_idx, nullptr, g3, be3, outE);
}